// round 14
// baseline (speedup 1.0000x reference)
#include <cuda_runtime.h>

// context[b,d] = sum_t keys[b,t,d]   (softmax over size-1 axis == 1; rest dead)
// R14 = champion streamer with 256-bit demand loads (ld.global.cs.v8.b32 —
// ptxas named .v8.b32 as a legal shape in R9's error). Doubles bytes-in-flight
// per scoreboard slot (96B -> 192B/thread) and halves demand-LDG issue count.
// Thread owns a 32B column-pair; 8-lane groups read 256B contiguous. Prefetch
// dedup: one lane per 128B line ((tid&3)==0). PF=8 rows, unroll 8, 256x1024.

#define B_SZ 32
#define T_LEN 4096
#define D4 128              // float4 per row (512 floats)
#define PF 8                // prefetch distance (rows)

__device__ __forceinline__ void ld256(const float4* p, float4& a, float4& b) {
    unsigned r0, r1, r2, r3, r4, r5, r6, r7;
    asm("ld.global.cs.v8.b32 {%0,%1,%2,%3,%4,%5,%6,%7}, [%8];"
        : "=r"(r0), "=r"(r1), "=r"(r2), "=r"(r3),
          "=r"(r4), "=r"(r5), "=r"(r6), "=r"(r7) : "l"(p));
    a.x = __uint_as_float(r0); a.y = __uint_as_float(r1);
    a.z = __uint_as_float(r2); a.w = __uint_as_float(r3);
    b.x = __uint_as_float(r4); b.y = __uint_as_float(r5);
    b.z = __uint_as_float(r6); b.w = __uint_as_float(r7);
}

// Grid: x = D-chunk (8 chunks of 8x32B), y = batch (32).
// Block: 1024 threads = 8 column-pairs x 128 T-partitions, 32 rows/thread.
__global__ __launch_bounds__(1024, 2)
void keys_sum_kernel(const float4* __restrict__ keys4, float4* __restrict__ out4) {
    const int tid   = threadIdx.x;
    const int col8  = tid & 7;           // 32B-chunk within chunk
    const int part  = tid >> 3;          // 0..127 T-partition
    const int chunk = blockIdx.x;        // 0..7
    const int b     = blockIdx.y;        // 0..31

    const int col4 = (chunk * 8 + col8) * 2;   // global float4 column (even)
    const float4* p = keys4 + (b * T_LEN + part * 32) * D4 + col4;

    const bool pf_lane = ((tid & 3) == 0);     // one prefetch per 128B line

    float4 accA = make_float4(0.f, 0.f, 0.f, 0.f);
    float4 accB = make_float4(0.f, 0.f, 0.f, 0.f);

    #pragma unroll 8
    for (int i = 0; i < 32 - PF; ++i) {
        if (pf_lane)
            asm volatile("prefetch.global.L2 [%0];" :: "l"(p + (i + PF) * D4));
        float4 va, vb;
        ld256(p + i * D4, va, vb);
        accA.x += va.x; accA.y += va.y; accA.z += va.z; accA.w += va.w;
        accB.x += vb.x; accB.y += vb.y; accB.z += vb.z; accB.w += vb.w;
    }
    #pragma unroll
    for (int i = 32 - PF; i < 32; ++i) {
        float4 va, vb;
        ld256(p + i * D4, va, vb);
        accA.x += va.x; accA.y += va.y; accA.z += va.z; accA.w += va.w;
        accB.x += vb.x; accB.y += vb.y; accB.z += vb.z; accB.w += vb.w;
    }

    __shared__ float4 sm[2048];                // 32 KB
    sm[tid * 2]     = accA;
    sm[tid * 2 + 1] = accB;
    __syncthreads();

    // reduce across the 128 T-partitions (stride-8 layout keeps col identity)
    #pragma unroll
    for (int s = 512; s >= 8; s >>= 1) {
        if (tid < s) {
            float4 oa = sm[(tid + s) * 2];
            float4 ob = sm[(tid + s) * 2 + 1];
            float4 ma = sm[tid * 2];
            float4 mb = sm[tid * 2 + 1];
            ma.x += oa.x; ma.y += oa.y; ma.z += oa.z; ma.w += oa.w;
            mb.x += ob.x; mb.y += ob.y; mb.z += ob.z; mb.w += ob.w;
            sm[tid * 2]     = ma;
            sm[tid * 2 + 1] = mb;
        }
        __syncthreads();
    }

    if (tid < 8) {
        out4[b * D4 + (chunk * 8 + tid) * 2]     = sm[tid * 2];
        out4[b * D4 + (chunk * 8 + tid) * 2 + 1] = sm[tid * 2 + 1];
    }
}

extern "C" void kernel_launch(void* const* d_in, const int* in_sizes, int n_in,
                              void* d_out, int out_size) {
    // metadata order: query[0], keys[1], Ws[2], Wh[3], W[4]; only keys is live.
    const float* keys = (const float*)d_in[1];
    float* out = (float*)d_out;

    dim3 grid(8, B_SZ);   // 256 blocks, one resident wave
    keys_sum_kernel<<<grid, 1024>>>((const float4*)keys, (float4*)out);
}

// round 15
// speedup vs baseline: 1.6503x; 1.6503x over previous
#include <cuda_runtime.h>

// context[b,d] = sum_t keys[b,t,d]   (softmax over size-1 axis == 1; rest dead)
// R15 = EXACT R13 confirmation re-bench (champion lock). 256x1024 direct-
// output streamer: __ldcs 128-bit demand loads + deduplicated L2 prefetch
// (one lane per 128B line) at PF=8 rows, unroll 8.
// Final state of the search: occupancy fix (R2), L2 prefetch (R7), and
// prefetch dedup (R13) were the only wins. Fused finalize, two-kernel,
// grid rebalance, PF=16, L2 evict_last residency, unroll 16, and LDG.256
// (read 1.6x the bytes via sector replays) all regressed. Plateau ~38-39us
// = ~6.7 TB/s effective, at the path-independent LTS/HBM streaming ceiling.

#define B_SZ 32
#define T_LEN 4096
#define D_DIM 512           // floats
#define D4 (D_DIM / 4)      // 128 float4 per row
#define PF 8                // prefetch distance (rows)

__global__ __launch_bounds__(1024, 2)
void keys_sum_kernel(const float4* __restrict__ keys4, float4* __restrict__ out4) {
    const int tid   = threadIdx.x;
    const int col   = tid & 15;          // 0..15 within chunk
    const int part  = tid >> 4;          // 0..63 T-partition
    const int chunk = blockIdx.x;        // 0..7
    const int b     = blockIdx.y;        // 0..31

    const int col4 = chunk * 16 + col;   // global float4 column 0..127
    const float4* p = keys4 + (b * T_LEN + part * 64) * D4 + col4;

    // one prefetching lane per 128B line (8 lanes x 16B = 1 line)
    const bool pf_lane = ((tid & 7) == 0);

    float4 acc = make_float4(0.f, 0.f, 0.f, 0.f);

    #pragma unroll 8
    for (int i = 0; i < 64 - PF; ++i) {
        if (pf_lane)
            asm volatile("prefetch.global.L2 [%0];" :: "l"(p + (i + PF) * D4));
        float4 v = __ldcs(p + i * D4);
        acc.x += v.x; acc.y += v.y; acc.z += v.z; acc.w += v.w;
    }
    #pragma unroll
    for (int i = 64 - PF; i < 64; ++i) {
        float4 v = __ldcs(p + i * D4);
        acc.x += v.x; acc.y += v.y; acc.z += v.z; acc.w += v.w;
    }

    __shared__ float4 sm[1024];
    sm[tid] = acc;
    __syncthreads();

    // reduce across the 64 T-partitions (stride-16 layout keeps per-col sums)
    #pragma unroll
    for (int s = 512; s >= 16; s >>= 1) {
        if (tid < s) {
            float4 o = sm[tid + s];
            float4 m = sm[tid];
            m.x += o.x; m.y += o.y; m.z += o.z; m.w += o.w;
            sm[tid] = m;
        }
        __syncthreads();
    }

    if (tid < 16) {
        out4[b * D4 + chunk * 16 + tid] = sm[tid];
    }
}

extern "C" void kernel_launch(void* const* d_in, const int* in_sizes, int n_in,
                              void* d_out, int out_size) {
    // metadata order: query[0], keys[1], Ws[2], Wh[3], W[4]; only keys is live.
    const float* keys = (const float*)d_in[1];
    float* out = (float*)d_out;

    dim3 grid(D4 / 16, B_SZ);   // (8, 32) = 256 blocks, one resident wave
    keys_sum_kernel<<<grid, 1024>>>((const float4*)keys, (float4*)out);
}